// round 3
// baseline (speedup 1.0000x reference)
#include <cuda_runtime.h>

#define THR 0.5f
#define MIN_JUMP_ENERGY 0.5f
#define MIN_VELOCITY_THRESHOLD 0.1f
#define MIN_WALL_JUMP_SPEED 1.0f

static constexpr int B = 32;
static constexpr int E = 100000;

__global__ __launch_bounds__(256) void edge_mask_kernel(
    const float4* __restrict__ feat,     // [B, E, 16] as [B*E*4] float4
    const float*  __restrict__ phys,     // [B, 18]
    const float*  __restrict__ base,     // [B, E]
    float*        __restrict__ out)      // [B, E]
{
    const int b    = blockIdx.y;
    const int lane = threadIdx.x & 31;
    const int warpRowBase = (blockIdx.x * blockDim.x + threadIdx.x - lane);  // 32 rows per warp
    // warpRowBase == global warp id * 32

    // Per-batch physics scalars (uniform)
    const float* p = phys + b * 18;
    const float vel  = p[2];
    const float wall = p[5];
    const float ke   = p[9];
    const float cj   = p[16];
    const float cwj  = p[17];

    const bool cj_low = (cj < THR);
    const bool d2u = (wall < THR) || (vel < MIN_VELOCITY_THRESHOLD);
    const bool d4u = (wall < THR) || ((cwj < THR) && (vel < MIN_WALL_JUMP_SPEED));

    const size_t bOff = (size_t)b * E;
    const float4* fB = feat + bOff * 4;

    // Coalesced base-mask load (front-batched for MLP)
    const int myRow = warpRowBase + lane;
    float bval = 0.0f;
    if (myRow < E) bval = base[bOff + myRow];

    // Coalesced feature loads: instr k covers rows warpRowBase+8k .. +8k+7.
    // Lane holds chunk (lane&3) of row warpRowBase + 8k + (lane>>2).
    float4 v[4];
    const int fbase = warpRowBase * 4;
    #pragma unroll
    for (int k = 0; k < 4; k++) {
        const int r = warpRowBase + 8 * k + (lane >> 2);
        if (r < E) v[k] = fB[fbase + 32 * k + lane];
        else       v[k] = make_float4(0.f, 0.f, 0.f, 0.f);
    }

    unsigned s[4];
    #pragma unroll
    for (int k = 0; k < 4; k++) {
        const float4 c = v[k];

        // role 0 (lane%4==0): cols 0-3 argmax, first-max-wins
        float m0 = c.x; int a0 = 0;
        if (c.y > m0) { m0 = c.y; a0 = 1; }
        if (c.z > m0) { m0 = c.z; a0 = 2; }
        if (c.w > m0) { m0 = c.w; a0 = 3; }
        // role 1: cols 4,5
        float m1 = c.x; int a1 = 4;
        if (c.y > m1) { m1 = c.y; a1 = 5; }
        // role 2: col 10 = c.z -> d5 bit
        const unsigned d5b = (ke < c.z * MIN_JUMP_ENERGY) ? 16u : 0u;
        // role 3: cols 12-15
        unsigned fl = 0;
        if (c.z > THR) fl |= 1u;                                    // c3: requires_jump
        if ((cj < THR) || (vel < c.x)) fl |= 2u;                    // d3
        if (c.w > THR) fl |= 4u;                                    // c4: requires_wall_contact
        const bool over  = (c.y > 0.0f) && (vel > c.y);
        const bool under = (!over) && (vel < c.x);
        if (over || under) fl |= 8u;                                // over|under

        const int role = lane & 3;
        const float    fpay = (role == 1) ? m1 : m0;
        const unsigned ipay = (role == 0) ? (unsigned)a0
                            : (role == 1) ? (unsigned)a1
                            : (role == 2) ? d5b : fl;

        // stage 1: pair exchange (0<->1 merge argmax; 2<->3 merge flag bits)
        const float    fo = __shfl_xor_sync(0xFFFFFFFFu, fpay, 1);
        const unsigned io = __shfl_xor_sync(0xFFFFFFFFu, ipay, 1);
        unsigned t;
        if ((lane & 2) == 0) {
            // argmax combine: m1 > m0 strictly -> take a1
            if ((lane & 1) == 0) t = (fo > fpay) ? io : ipay;   // I am role0
            else                 t = (fpay > fo) ? ipay : io;   // I am role1
        } else {
            t = ipay | io;                                      // merged d5|flags
        }
        // stage 2: cross-pair exchange -> every lane has (et, flags)
        const unsigned o2 = __shfl_xor_sync(0xFFFFFFFFu, t, 2);
        const unsigned et = ((lane & 2) == 0) ? t : o2;
        const unsigned fg = ((lane & 2) == 0) ? o2 : t;

        const bool c1 = (et == 1u) && cj_low;
        const bool c2 = (et == 3u);
        const bool c3 = (fg & 1u);
        const bool d3 = (fg & 2u);
        const bool c4 = (fg & 4u);
        const bool ou = (fg & 8u);
        const bool d5 = (fg & 16u);

        bool dis;
        if      (c1) dis = true;
        else if (c2) dis = d2u;
        else if (c3) dis = d3;
        else if (c4) dis = d4u;
        else if (et == 1u) dis = d5;
        else dis = false;
        dis = dis || ou;

        s[k] = dis ? 1u : 0u;
    }

    // Redistribute: row (warpRowBase + L) flag lives in s[L>>3] of lane 4*(L&7).
    unsigned g0 = __shfl_sync(0xFFFFFFFFu, s[0], (lane & 7) * 4);
    unsigned g1 = __shfl_sync(0xFFFFFFFFu, s[1], (lane & 7) * 4);
    unsigned g2 = __shfl_sync(0xFFFFFFFFu, s[2], (lane & 7) * 4);
    unsigned g3 = __shfl_sync(0xFFFFFFFFu, s[3], (lane & 7) * 4);
    const int sel = lane >> 3;
    const unsigned dis = (sel == 0) ? g0 : (sel == 1) ? g1 : (sel == 2) ? g2 : g3;

    if (myRow < E) out[bOff + myRow] = dis ? 0.0f : bval;
}

extern "C" void kernel_launch(void* const* d_in, const int* in_sizes, int n_in,
                              void* d_out, int out_size)
{
    const float4* feat = (const float4*)d_in[0];
    const float*  phys = (const float*) d_in[1];
    const float*  base = (const float*) d_in[2];
    float*        out  = (float*)d_out;

    dim3 block(256);
    dim3 grid((E + 255) / 256, B);
    edge_mask_kernel<<<grid, block>>>(feat, phys, base, out);
}

// round 4
// speedup vs baseline: 1.3861x; 1.3861x over previous
#include <cuda_runtime.h>

#define THR 0.5f
#define MIN_JUMP_ENERGY 0.5f
#define MIN_VELOCITY_THRESHOLD 0.1f
#define MIN_WALL_JUMP_SPEED 1.0f

static constexpr int B = 32;
static constexpr int E = 100000;   // divisible by 32: warps are all-in or all-out

__global__ __launch_bounds__(256) void edge_mask_kernel(
    const float4* __restrict__ feat,     // [B, E, 16] as float4[B*E*4]
    const float*  __restrict__ phys,     // [B, 18]
    const float*  __restrict__ base,     // [B, E]
    float*        __restrict__ out)      // [B, E]
{
    __shared__ float4 sh[8][128];        // 2 KB per warp, 16 KB per block

    const int b    = blockIdx.y;
    const int warp = threadIdx.x >> 5;
    const int lane = threadIdx.x & 31;
    const int warpRowBase = blockIdx.x * 256 + warp * 32;
    if (warpRowBase >= E) return;        // whole-warp uniform (E % 32 == 0)

    // Per-batch physics scalars (uniform, L1/L2-resident)
    const float* p = phys + b * 18;
    const float vel  = p[2];
    const float wall = p[5];
    const float ke   = p[9];
    const float cj   = p[16];
    const float cwj  = p[17];

    const size_t  bOff = (size_t)b * E;
    const float4* fB   = feat + (bOff + (size_t)warpRowBase) * 4;

    // Front-batched loads: 1 coalesced base + 4 coalesced 512B feature loads
    const float bval = base[bOff + warpRowBase + lane];

    float4 v[4];
    #pragma unroll
    for (int k = 0; k < 4; k++)
        v[k] = fB[k * 32 + lane];

    // Swizzled store: flat chunk index i = row*4 + chunk; sw(i) = i ^ ((i>>2)&7)
    float4* s = sh[warp];
    #pragma unroll
    for (int k = 0; k < 4; k++) {
        const int i = k * 32 + lane;
        s[i ^ ((i >> 2) & 7)] = v[k];
    }
    __syncwarp();

    // Swizzled read: this thread's row = lane; chunks 0..3
    float4 c0, c1, c2, c3;
    {
        const int i0 = lane * 4 + 0;
        const int i1 = lane * 4 + 1;
        const int i2 = lane * 4 + 2;
        const int i3 = lane * 4 + 3;
        c0 = s[i0 ^ ((i0 >> 2) & 7)];
        c1 = s[i1 ^ ((i1 >> 2) & 7)];
        c2 = s[i2 ^ ((i2 >> 2) & 7)];
        c3 = s[i3 ^ ((i3 >> 2) & 7)];
    }

    // argmax over cols 0..5, first-max-wins (strict >)
    int   et = 0;
    float mx = c0.x;
    if (c0.y > mx) { mx = c0.y; et = 1; }
    if (c0.z > mx) { mx = c0.z; et = 2; }
    if (c0.w > mx) { mx = c0.w; et = 3; }
    if (c1.x > mx) { mx = c1.x; et = 4; }
    if (c1.y > mx) { mx = c1.y; et = 5; }

    const float energy_cost           = c2.z;  // col 10
    const float min_velocity          = c3.x;  // col 12
    const float max_velocity          = c3.y;  // col 13
    const float requires_jump         = c3.z;  // col 14
    const float requires_wall_contact = c3.w;  // col 15

    // jnp.select: first-true-wins priority chain
    const bool cc1 = (et == 1) && (cj < THR);
    const bool cc2 = (et == 3);
    const bool d2  = (wall < THR) || (vel < MIN_VELOCITY_THRESHOLD);
    const bool cc3 = (requires_jump > THR);
    const bool d3  = (cj < THR) || (vel < min_velocity);
    const bool cc4 = (requires_wall_contact > THR);
    const bool d4  = (wall < THR) ||
                     ((cwj < THR) && (vel < MIN_WALL_JUMP_SPEED));
    const bool cc5 = (et == 1);
    const bool d5  = (ke < energy_cost * MIN_JUMP_ENERGY);

    bool dis;
    if      (cc1) dis = true;
    else if (cc2) dis = d2;
    else if (cc3) dis = d3;
    else if (cc4) dis = d4;
    else if (cc5) dis = d5;
    else          dis = false;

    const bool over  = (max_velocity > 0.0f) && (vel > max_velocity);
    const bool under = (!over) && (vel < min_velocity);
    dis = dis || over || under;

    out[bOff + warpRowBase + lane] = dis ? 0.0f : bval;
}

extern "C" void kernel_launch(void* const* d_in, const int* in_sizes, int n_in,
                              void* d_out, int out_size)
{
    const float4* feat = (const float4*)d_in[0];
    const float*  phys = (const float*) d_in[1];
    const float*  base = (const float*) d_in[2];
    float*        out  = (float*)d_out;

    dim3 block(256);
    dim3 grid((E + 255) / 256, B);
    edge_mask_kernel<<<grid, block>>>(feat, phys, base, out);
}